// round 8
// baseline (speedup 1.0000x reference)
#include <cuda_runtime.h>
#include <cstdint>

// Depthwise cross-correlation (XLA conv semantics, no kernel flip):
//   out[ch, ho, wo] = sum_{ky<7, kx<7} x[ch, ho+ky, wo+kx] * z[ch, ky, kx]
// x: [32768, 31, 31], z: [32768, 7, 7], out: [32768, 25, 25], all fp32.
//
// v6 = v5 (62us) made persistent: each warp walks ~11 channels grid-stride,
// double-buffering the x tile via cp.async so the per-channel DRAM round trip
// overlaps the previous channel's compute. All sync is warp-local.
//
// Per channel per warp: 25 active lanes, one output column each, 25 packed
// f32x2 row accumulators; per ky: 3 aligned LDS.64 + 1 LDS.32 feeding
// 3 fma.f32x2 + 1 scalar fma.

#define HX 31
#define WX 31
#define HZ 7
#define WZ 7
#define HO 25
#define WO 25
#define XPAD 32
#define WARPS 4
#define NCH (128 * 256)

__device__ __forceinline__ void fma2(float2 &d, unsigned long long a,
                                     unsigned long long b) {
    unsigned long long dd = *reinterpret_cast<unsigned long long*>(&d);
    asm("fma.rn.f32x2 %0, %1, %2, %0;" : "+l"(dd) : "l"(a), "l"(b));
    d = *reinterpret_cast<float2*>(&dd);
}

__device__ __forceinline__ unsigned long long lds2(const float* p) {
    return *reinterpret_cast<const unsigned long long*>(p);
}

__device__ __forceinline__ uint32_t smem_u32(const void* p) {
    uint32_t a;
    asm("{ .reg .u64 t; cvta.to.shared.u64 t, %1; cvt.u32.u64 %0, t; }"
        : "=r"(a) : "l"(p));
    return a;
}

__device__ __forceinline__ void cp4(uint32_t dst, const float* src) {
    asm volatile("cp.async.ca.shared.global [%0], [%1], 4;"
                 :: "r"(dst), "l"(src));
}

__device__ __forceinline__ void prefetch_x(uint32_t sbase, const float* xch,
                                           int lane) {
    if (lane < WX) {
#pragma unroll
        for (int r = 0; r < HX; r++)
            cp4(sbase + (uint32_t)(r * XPAD + lane) * 4u, xch + r * WX + lane);
    }
    asm volatile("cp.async.commit_group;" ::: "memory");
}

__global__ void __launch_bounds__(128, 5)
dwxcorr_v6(const float* __restrict__ zf,
           const float* __restrict__ xf,
           float* __restrict__ out) {
    __shared__ __align__(16) float sx[WARPS][2][HX][XPAD];   // double-buffered x
    __shared__ __align__(16) float sk[WARPS][2][HZ][8];      // taps (single buf)

    const int tid  = threadIdx.x;
    const int warp = tid >> 5;
    const int lane = tid & 31;
    const int W    = blockIdx.x * WARPS + warp;   // global warp id
    const int NW   = gridDim.x * WARPS;           // warp stride over channels

    const uint32_t sb[2] = { smem_u32(&sx[warp][0][0][0]),
                             smem_u32(&sx[warp][1][0][0]) };

    // lane -> (ky,j) decomposition for tap scatter (computed once)
    const int t0ky = lane / WZ,        t0j = lane - t0ky * WZ;        // z[lane]
    const int t1ky = (lane + 25) / WZ, t1j = (lane + 25) - t1ky * WZ; // z[lane+25]

    // ---- prime the pipeline: channel W ----
    float z0 = 0.0f, z1 = 0.0f;
    if (W < NCH) {
        prefetch_x(sb[0], xf + (long long)W * (HX * WX), lane);
        const float* zc = zf + (long long)W * (HZ * WZ);
        if (lane < 25) z0 = zc[lane];
        if (lane < 24) z1 = zc[lane + 25];
    }

    const int par = lane & 1;
    const int B   = (lane & ~1) + 2 * par;   // pair-load base (8B aligned)
    const int S   = lane + 6 * (1 - par);    // scalar x column
    const int pofs = 2 * par;
    const int sofs = 6 - 5 * par;

    int buf = 0;
    for (int ch = W; ch < NCH; ch += NW, buf ^= 1) {
        // ---- scatter current taps (regs -> parity-shifted smem copies) ----
        // copy0: [k0..k6 0]   copy1: [0 k0..k6]
        if (lane < 25) { sk[warp][0][t0ky][t0j] = z0; sk[warp][1][t0ky][t0j + 1] = z0; }
        if (lane < 24) { sk[warp][0][t1ky][t1j] = z1; sk[warp][1][t1ky][t1j + 1] = z1; }
        if (lane < HZ) { sk[warp][0][lane][7] = 0.0f; sk[warp][1][lane][0] = 0.0f; }

        // ---- prefetch next channel into the other buffer ----
        const int nch = ch + NW;
        if (nch < NCH) {
            prefetch_x(sb[buf ^ 1], xf + (long long)nch * (HX * WX), lane);
            const float* zn = zf + (long long)nch * (HZ * WZ);
            if (lane < 25) z0 = zn[lane];
            if (lane < 24) z1 = zn[lane + 25];
            asm volatile("cp.async.wait_group 1;" ::: "memory"); // current done
        } else {
            asm volatile("cp.async.wait_group 0;" ::: "memory");
        }
        __syncwarp();

        // ---- compute channel ch from sx[warp][buf] ----
        if (lane < WO) {
            unsigned long long kp[HZ][3];
            float ks[HZ];
#pragma unroll
            for (int ky = 0; ky < HZ; ky++) {
#pragma unroll
                for (int j = 0; j < 3; j++)
                    kp[ky][j] = lds2(&sk[warp][par][ky][pofs + 2 * j]);
                ks[ky] = sk[warp][par][ky][sofs];
            }

            float2 acc[HO];
#pragma unroll
            for (int i = 0; i < HO; i++) acc[i] = make_float2(0.0f, 0.0f);

            const float* __restrict__ sxw = &sx[warp][buf][0][0];
#pragma unroll
            for (int r = 0; r < HX; r++) {
                const float* row = sxw + r * XPAD;
                const unsigned long long p0 = lds2(row + B);
                const unsigned long long p1 = lds2(row + B + 2);
                const unsigned long long p2 = lds2(row + B + 4);
                const float xs = row[S];
#pragma unroll
                for (int ky = 0; ky < HZ; ky++) {
                    const int ho = r - ky;
                    if (ho >= 0 && ho < HO) {
                        fma2(acc[ho], p0, kp[ky][0]);
                        fma2(acc[ho], p1, kp[ky][1]);
                        fma2(acc[ho], p2, kp[ky][2]);
                        acc[ho].x = fmaf(xs, ks[ky], acc[ho].x);
                    }
                }
            }

            float* __restrict__ och = out + (long long)ch * (HO * WO) + lane;
#pragma unroll
            for (int ho = 0; ho < HO; ho++)
                och[ho * WO] = acc[ho].x + acc[ho].y;
        }
        __syncwarp();   // reads of sx[buf]/sk done before next iter overwrites
    }
}

extern "C" void kernel_launch(void* const* d_in, const int* in_sizes, int n_in,
                              void* d_out, int out_size) {
    // metadata order: z_f [128,256,7,7] then x_f [128,256,31,31]
    const float* z = (const float*)d_in[0];
    const float* x = (const float*)d_in[1];
    if (n_in >= 2 && in_sizes[0] > in_sizes[1]) {   // defensive: z is the small one
        const float* t = z; z = x; x = t;
    }
    float* o = (float*)d_out;

    int sms = 148;
    cudaDeviceGetAttribute(&sms, cudaDevAttrMultiProcessorCount, 0);
    dim3 grid(sms * 5);          // fully resident persistent CTAs
    dim3 block(128);
    dwxcorr_v6<<<grid, block>>>(z, x, o);
}

// round 10
// speedup vs baseline: 1.1146x; 1.1146x over previous
#include <cuda_runtime.h>
#include <cstdint>

// Depthwise cross-correlation (XLA conv semantics, no kernel flip):
//   out[ch, ho, wo] = sum_{ky<7, kx<7} x[ch, ho+ky, wo+kx] * z[ch, ky, kx]
// x: [32768, 31, 31], z: [32768, 7, 7], out: [32768, 25, 25], all fp32.
//
// v7 = v5 (62us) with the per-CTA DRAM prologue amortized over 2 channels:
// each warp prefetches BOTH of its channels' x tiles via cp.async up-front
// (two groups), computes channel A while channel B's copy flies. CTAs stay
// oversubscribed (4096) so the hardware scheduler keeps waves staggered
// (v6's persistent lockstep regression showed that stagger matters).
//
// Per channel per warp: 25 active lanes, one output column each, 25 packed
// f32x2 row accumulators; per (row,ky): 3 aligned LDS.64 + 1 LDS.32 feed
// 3 fma.f32x2 + 1 scalar fma (100% MAC-slot efficiency).

#define HX 31
#define WX 31
#define HZ 7
#define WZ 7
#define HO 25
#define WO 25
#define XPAD 32
#define WARPS 4
#define NCH (128 * 256)

__device__ __forceinline__ void fma2(float2 &d, unsigned long long a,
                                     unsigned long long b) {
    unsigned long long dd = *reinterpret_cast<unsigned long long*>(&d);
    asm("fma.rn.f32x2 %0, %1, %2, %0;" : "+l"(dd) : "l"(a), "l"(b));
    d = *reinterpret_cast<float2*>(&dd);
}

__device__ __forceinline__ unsigned long long lds2(const float* p) {
    return *reinterpret_cast<const unsigned long long*>(p);
}

__device__ __forceinline__ uint32_t smem_u32(const void* p) {
    uint32_t a;
    asm("{ .reg .u64 t; cvta.to.shared.u64 t, %1; cvt.u32.u64 %0, t; }"
        : "=r"(a) : "l"(p));
    return a;
}

__device__ __forceinline__ void cp4(uint32_t dst, const float* src) {
    asm volatile("cp.async.ca.shared.global [%0], [%1], 4;"
                 :: "r"(dst), "l"(src));
}

__device__ __forceinline__ void prefetch_x(uint32_t sbase, const float* xch,
                                           int lane) {
    if (lane < WX) {
#pragma unroll
        for (int r = 0; r < HX; r++)
            cp4(sbase + (uint32_t)(r * XPAD + lane) * 4u, xch + r * WX + lane);
    }
    asm volatile("cp.async.commit_group;" ::: "memory");
}

// compute one channel from staged smem and store its 25x25 output tile
__device__ __forceinline__ void compute_store(
    const float* __restrict__ sxw,          // [31][XPAD] x tile
    const float (*__restrict__ skp)[8],     // [7][8] parity tap copy
    int B, int S, int pofs, int sofs, int lane,
    float* __restrict__ och) {
    unsigned long long kp[HZ][3];
    float ks[HZ];
#pragma unroll
    for (int ky = 0; ky < HZ; ky++) {
#pragma unroll
        for (int j = 0; j < 3; j++)
            kp[ky][j] = lds2(&skp[ky][pofs + 2 * j]);
        ks[ky] = skp[ky][sofs];
    }

    float2 acc[HO];
#pragma unroll
    for (int i = 0; i < HO; i++) acc[i] = make_float2(0.0f, 0.0f);

#pragma unroll
    for (int r = 0; r < HX; r++) {
        const float* row = sxw + r * XPAD;
        const unsigned long long p0 = lds2(row + B);
        const unsigned long long p1 = lds2(row + B + 2);
        const unsigned long long p2 = lds2(row + B + 4);
        const float xs = row[S];
#pragma unroll
        for (int ky = 0; ky < HZ; ky++) {
            const int ho = r - ky;
            if (ho >= 0 && ho < HO) {
                fma2(acc[ho], p0, kp[ky][0]);
                fma2(acc[ho], p1, kp[ky][1]);
                fma2(acc[ho], p2, kp[ky][2]);
                acc[ho].x = fmaf(xs, ks[ky], acc[ho].x);   // lo+hi commute
            }
        }
    }

#pragma unroll
    for (int ho = 0; ho < HO; ho++)
        och[ho * WO] = acc[ho].x + acc[ho].y;
}

__global__ void __launch_bounds__(128, 5)
dwxcorr_v7(const float* __restrict__ zf,
           const float* __restrict__ xf,
           float* __restrict__ out) {
    __shared__ __align__(16) float sx[WARPS][2][HX][XPAD];   // 2 channel bufs
    __shared__ __align__(16) float sk[WARPS][2][2][HZ][8];   // [chbuf][parity]

    const int tid  = threadIdx.x;
    const int warp = tid >> 5;
    const int lane = tid & 31;
    const int c0   = blockIdx.x * (2 * WARPS) + warp;   // first channel
    const int c1   = c0 + WARPS;                        // second channel

    // ---- prefetch both x tiles (2 groups) + both tap sets, all in flight ----
    prefetch_x(smem_u32(&sx[warp][0][0][0]), xf + (long long)c0 * (HX * WX), lane);
    prefetch_x(smem_u32(&sx[warp][1][0][0]), xf + (long long)c1 * (HX * WX), lane);

    const float* zA = zf + (long long)c0 * (HZ * WZ);
    const float* zB = zf + (long long)c1 * (HZ * WZ);
    float a0 = 0.f, a1 = 0.f, b0 = 0.f, b1 = 0.f;
    if (lane < 25) { a0 = zA[lane];      b0 = zB[lane]; }
    if (lane < 24) { a1 = zA[lane + 25]; b1 = zB[lane + 25]; }

    // lane -> (ky,j) for tap scatter
    const int t0ky = lane / WZ,        t0j = lane - t0ky * WZ;
    const int t1ky = (lane + 25) / WZ, t1j = (lane + 25) - t1ky * WZ;

    // ---- scatter both tap sets into parity-shifted copies ----
    // copy0: [k0..k6 0]   copy1: [0 k0..k6]
    if (lane < 25) {
        sk[warp][0][0][t0ky][t0j] = a0;  sk[warp][0][1][t0ky][t0j + 1] = a0;
        sk[warp][1][0][t0ky][t0j] = b0;  sk[warp][1][1][t0ky][t0j + 1] = b0;
    }
    if (lane < 24) {
        sk[warp][0][0][t1ky][t1j] = a1;  sk[warp][0][1][t1ky][t1j + 1] = a1;
        sk[warp][1][0][t1ky][t1j] = b1;  sk[warp][1][1][t1ky][t1j + 1] = b1;
    }
    if (lane < HZ) {
        sk[warp][0][0][lane][7] = 0.f;   sk[warp][0][1][lane][0] = 0.f;
        sk[warp][1][0][lane][7] = 0.f;   sk[warp][1][1][lane][0] = 0.f;
    }

    const int par  = lane & 1;
    const int B    = (lane & ~1) + 2 * par;   // pair-load base (8B aligned)
    const int S    = lane + 6 * (1 - par);    // scalar x column
    const int pofs = 2 * par;
    const int sofs = 6 - 5 * par;

    // ---- channel A: wait only for group 0 (group 1 still flying) ----
    asm volatile("cp.async.wait_group 1;" ::: "memory");
    __syncwarp();
    if (lane < WO)
        compute_store(&sx[warp][0][0][0], sk[warp][0][par], B, S, pofs, sofs,
                      lane, out + (long long)c0 * (HO * WO) + lane);

    // ---- channel B ----
    asm volatile("cp.async.wait_group 0;" ::: "memory");
    __syncwarp();
    if (lane < WO)
        compute_store(&sx[warp][1][0][0], sk[warp][1][par], B, S, pofs, sofs,
                      lane, out + (long long)c1 * (HO * WO) + lane);
}

extern "C" void kernel_launch(void* const* d_in, const int* in_sizes, int n_in,
                              void* d_out, int out_size) {
    // metadata order: z_f [128,256,7,7] then x_f [128,256,31,31]
    const float* z = (const float*)d_in[0];
    const float* x = (const float*)d_in[1];
    if (n_in >= 2 && in_sizes[0] > in_sizes[1]) {   // defensive: z is the small one
        const float* t = z; z = x; x = t;
    }
    float* o = (float*)d_out;

    dim3 grid(NCH / (2 * WARPS));   // 4096 CTAs, 2 channels per warp
    dim3 block(128);
    dwxcorr_v7<<<grid, block>>>(z, x, o);
}